// round 10
// baseline (speedup 1.0000x reference)
#include <cuda_runtime.h>
#include <cstdint>

#define H        2048
#define E        64
#define M_TILE   128
#define NT       64      // k tiles of 32
#define NTHREADS 512

// Prep outputs (static device scratch)
__device__ float g_wp[H * E];   // permuted: chunk(kt,kb, i=e&7, tx=e>>3)[kq]
__device__ float g_c[E];        // sum_h gate[e][h]*w[h]
__device__ float g_d[E];        // sum_h ln_bias[h]*gate[e][h]

// ---------------------------------------------------------------------------
// prep: fold ln_weight into gate, permute for conflict-free compute loads
// element (e, k) -> g_wp[(((k>>5)*8 + ((k>>2)&7))*64 + (e&7)*8 + (e>>3))*4 + (k&3)]
// ---------------------------------------------------------------------------
__global__ void prep_kernel(const float* __restrict__ gate,
                            const float* __restrict__ w,
                            const float* __restrict__ b) {
    int e = blockIdx.x;
    int t = threadIdx.x;
    int ei = e & 7, txe = e >> 3;
    float sc = 0.f, sd = 0.f;
    for (int k = t; k < H; k += 256) {
        float gv = gate[e * H + k];
        float p  = gv * w[k];
        int kt = k >> 5, kb = (k >> 2) & 7, kq = k & 3;
        g_wp[(((kt * 8 + kb) * 64) + ei * 8 + txe) * 4 + kq] = p;
        sc += p;
        sd += b[k] * gv;
    }
    __shared__ float rs[256], rd[256];
    rs[t] = sc; rd[t] = sd;
    __syncthreads();
    for (int s = 128; s > 0; s >>= 1) {
        if (t < s) { rs[t] += rs[t + s]; rd[t] += rd[t + s]; }
        __syncthreads();
    }
    if (t == 0) { g_c[e] = rs[0]; g_d[e] = rd[0]; }
}

// packed f32x2 FMA (Blackwell): d = a*b + d elementwise on float pairs
__device__ __forceinline__ void ffma2(unsigned long long& d,
                                      unsigned long long a,
                                      unsigned long long b) {
    asm("fma.rn.f32x2 %0, %1, %2, %0;" : "+l"(d) : "l"(a), "l"(b));
}

// ---------------------------------------------------------------------------
// main: fused stats + GEMM (k-packed f32x2) + softmax + top2
// grid = 128 blocks x 512 threads; thread tile = 2 rows x 8 experts
// tx = t&7 -> experts [8tx, 8tx+8);  r0 = (t>>3)*2 -> rows r0, r0+1
// x smem (double buffer): slot = kb*128 + (row ^ kb)
// w smem (3-stage cp.async ring): slot = kb*64 + (e&7)*8 + (e>>3)
// ONE __syncthreads per k-tile.
// ---------------------------------------------------------------------------
__global__ __launch_bounds__(NTHREADS, 1)
void router_kernel(const float* __restrict__ X, float* __restrict__ out,
                   int n_rows) {
    __shared__ float4 s_x[2][8 * 128];     // 32 KB (double buffer)
    __shared__ float4 s_w[3][8 * 64];      // 24 KB (cp.async 3-ring)
    __shared__ float s_mu[M_TILE], s_rstd[M_TILE];

    const int t = threadIdx.x;
    const int row_base = blockIdx.x * M_TILE;
    const int tx = t & 7;
    const int r0 = (t >> 3) * 2;
    const int lrow = t >> 2;       // loader: 0..127 (one row per thread)
    const int lkq  = t & 3;        // loader: k segment (8 floats)

    uint32_t w_smem[3];
#pragma unroll
    for (int i = 0; i < 3; i++)
        w_smem[i] = (uint32_t)__cvta_generic_to_shared(&s_w[i][0]);

    const float* xg0 = X + (size_t)(row_base + lrow) * H + lkq * 8;

    unsigned long long acc[8][2];
#pragma unroll
    for (int a = 0; a < 8; a++) { acc[a][0] = 0ull; acc[a][1] = 0ull; }

    float st_s = 0.f, st_q = 0.f;
    float4 xs[2];

    // prologue: w tile 0 via cp.async (ring 0), x tile 0 via LDG
    {
        const float* wsrc = g_wp + t * 4;
        asm volatile("cp.async.cg.shared.global [%0], [%1], 16;\n"
                     :: "r"(w_smem[0] + t * 16), "l"(wsrc));
        asm volatile("cp.async.commit_group;\n" ::: "memory");
#pragma unroll
        for (int q = 0; q < 2; q++)
            xs[q] = *(const float4*)(xg0 + q * 4);
    }

    for (int kt = 0; kt < NT; ++kt) {
        const int xb = kt & 1;
        // store x tile kt (swizzled) + accumulate LN stats from registers
#pragma unroll
        for (int q = 0; q < 2; q++) {
            int kb = 2 * lkq + q;
            s_x[xb][kb * 128 + (lrow ^ kb)] = xs[q];
            float4 v = xs[q];
            st_s += (v.x + v.y) + (v.z + v.w);
            st_q += v.x * v.x + v.y * v.y + v.z * v.z + v.w * v.w;
        }
        // prefetch next tile: w -> next ring stage, x -> registers
        if (kt + 1 < NT) {
            const float* wsrc = g_wp + (size_t)(kt + 1) * 2048 + t * 4;
            int wi = (kt + 1) % 3;
            asm volatile("cp.async.cg.shared.global [%0], [%1], 16;\n"
                         :: "r"(w_smem[wi] + t * 16), "l"(wsrc));
            asm volatile("cp.async.commit_group;\n" ::: "memory");
            const float* xgn = xg0 + (size_t)(kt + 1) * 32;
#pragma unroll
            for (int q = 0; q < 2; q++)
                xs[q] = *(const float4*)(xgn + q * 4);
            asm volatile("cp.async.wait_group 1;\n" ::: "memory");
        } else {
            asm volatile("cp.async.wait_group 0;\n" ::: "memory");
        }
        __syncthreads();

        // compute: 8 steps of 4 k; 10 LDS.128 + 32 FFMA2 per step per thread
        const float4* wb = s_w[kt % 3];
#pragma unroll
        for (int kb = 0; kb < 8; kb++) {
            ulonglong2 xv0 = *(const ulonglong2*)&s_x[xb][kb * 128 + ((r0 + 0) ^ kb)];
            ulonglong2 xv1 = *(const ulonglong2*)&s_x[xb][kb * 128 + ((r0 + 1) ^ kb)];
            ulonglong2 wv[8];
#pragma unroll
            for (int i = 0; i < 8; i++)
                wv[i] = *(const ulonglong2*)&wb[kb * 64 + i * 8 + tx];
#pragma unroll
            for (int ei = 0; ei < 8; ei++) {
                ffma2(acc[ei][0], xv0.x, wv[ei].x);
                ffma2(acc[ei][0], xv0.y, wv[ei].y);
                ffma2(acc[ei][1], xv1.x, wv[ei].x);
                ffma2(acc[ei][1], xv1.y, wv[ei].y);
            }
        }
    }

    // finalize LN stats (loader partners: lanes differing in bits 0-1)
    {
        float s = st_s, qq = st_q;
        s  += __shfl_xor_sync(0xffffffffu, s, 1);
        qq += __shfl_xor_sync(0xffffffffu, qq, 1);
        s  += __shfl_xor_sync(0xffffffffu, s, 2);
        qq += __shfl_xor_sync(0xffffffffu, qq, 2);
        if (lkq == 0) {
            float mu  = s * (1.0f / H);
            float var = qq * (1.0f / H) - mu * mu;
            s_mu[lrow]   = mu;
            s_rstd[lrow] = rsqrtf(var + 1e-5f);
        }
    }
    __syncthreads();

    float cc[8], dd[8];
#pragma unroll
    for (int i = 0; i < 8; i++) { cc[i] = g_c[8 * tx + i]; dd[i] = g_d[8 * tx + i]; }

    float* out_p = out;                         // (N,2) normalized top-2 probs
    float* out_i = out + (size_t)n_rows * 2;    // (N,2) indices (as float)
    float* out_l = out + (size_t)n_rows * 4;    // (N,64) logits

#pragma unroll
    for (int ri = 0; ri < 2; ri++) {
        int row  = r0 + ri;
        int grow = row_base + row;
        float mu   = s_mu[row];
        float rstd = s_rstd[row];
        float l[8];
#pragma unroll
        for (int ei = 0; ei < 8; ei++) {
            unsigned long long v = acc[ei][ri];
            float lv = __uint_as_float((unsigned int)(v & 0xffffffffull)) +
                       __uint_as_float((unsigned int)(v >> 32));
            lv = rstd * (lv - mu * cc[ei]) + dd[ei];
            l[ei] = fminf(fmaxf(lv, -10.0f), 10.0f);
        }
        *(float4*)&out_l[(size_t)grow * 64 + 8 * tx]     = make_float4(l[0], l[1], l[2], l[3]);
        *(float4*)&out_l[(size_t)grow * 64 + 8 * tx + 4] = make_float4(l[4], l[5], l[6], l[7]);

        // row max over 64 (8 local + width-8 butterfly over tx)
        float m = l[0];
#pragma unroll
        for (int i = 1; i < 8; i++) m = fmaxf(m, l[i]);
#pragma unroll
        for (int s8 = 4; s8; s8 >>= 1)
            m = fmaxf(m, __shfl_xor_sync(0xffffffffu, m, s8));

        float ev[8];
        float s = 0.f;
#pragma unroll
        for (int i = 0; i < 8; i++) { ev[i] = expf(l[i] - m); s += ev[i]; }
#pragma unroll
        for (int s8 = 4; s8; s8 >>= 1)
            s += __shfl_xor_sync(0xffffffffu, s, s8);

        // local top-2 (clip to [1e-4, 1] first, as reference does)
        float v1 = -1.f, v2 = -1.f; int i1 = 0, i2 = 0;
#pragma unroll
        for (int i = 0; i < 8; i++) {
            float p = ev[i] / s;
            p = fminf(fmaxf(p, 1e-4f), 1.0f);
            int gi = 8 * tx + i;
            if (p > v1) { v2 = v1; i2 = i1; v1 = p; i1 = gi; }
            else if (p > v2) { v2 = p; i2 = gi; }
        }
        // butterfly merge of top-2 lists, tie-break on lower index (jax top_k)
#pragma unroll
        for (int s8 = 4; s8; s8 >>= 1) {
            float u1 = __shfl_xor_sync(0xffffffffu, v1, s8);
            int   j1 = __shfl_xor_sync(0xffffffffu, i1, s8);
            float u2 = __shfl_xor_sync(0xffffffffu, v2, s8);
            int   j2 = __shfl_xor_sync(0xffffffffu, i2, s8);
            bool afirst = (v1 > u1) || (v1 == u1 && i1 < j1);
            float w1 = afirst ? v1 : u1;  int k1 = afirst ? i1 : j1;
            float ca = afirst ? v2 : u2;  int kca = afirst ? i2 : j2;  // winner's 2nd
            float cb = afirst ? u1 : v1;  int kcb = afirst ? j1 : i1;  // loser's 1st
            bool bsec = (cb > ca) || (cb == ca && kcb < kca);
            float w2 = bsec ? cb : ca;    int k2 = bsec ? kcb : kca;
            v1 = w1; i1 = k1; v2 = w2; i2 = k2;
        }
        if (tx == 0) {
            float ps = fmaxf(v1 + v2, 1e-4f);
            out_p[(size_t)grow * 2 + 0] = v1 / ps;
            out_p[(size_t)grow * 2 + 1] = v2 / ps;
            out_i[(size_t)grow * 2 + 0] = (float)i1;
            out_i[(size_t)grow * 2 + 1] = (float)i2;
        }
    }
}

extern "C" void kernel_launch(void* const* d_in, const int* in_sizes, int n_in,
                              void* d_out, int out_size) {
    const float* X = (const float*)d_in[0];   // hidden_states (4,4096,2048)
    const float* w = (const float*)d_in[1];   // ln_weight (2048)
    const float* b = (const float*)d_in[2];   // ln_bias (2048)
    const float* g = (const float*)d_in[3];   // gate_weight (64,2048)
    int n_rows = in_sizes[0] / H;             // 16384

    prep_kernel<<<E, 256>>>(g, w, b);
    router_kernel<<<n_rows / M_TILE, NTHREADS>>>(X, (float*)d_out, n_rows);
}

// round 12
// speedup vs baseline: 1.3196x; 1.3196x over previous
#include <cuda_runtime.h>
#include <cstdint>

#define H        2048
#define E        64
#define M_TILE   128
#define NT       64      // k tiles of 32
#define NTHREADS 256

// Prep outputs (static device scratch)
__device__ float g_wp[H * E];   // permuted: chunk(kt,kb, i=e&7, tx=e>>3)[kq]
__device__ float g_c[E];        // sum_h gate[e][h]*w[h]
__device__ float g_d[E];        // sum_h ln_bias[h]*gate[e][h]

// ---------------------------------------------------------------------------
// prep: fold ln_weight into gate, permute for conflict-free compute loads
// element (e, k) -> g_wp[(((k>>5)*8 + ((k>>2)&7))*64 + (e&7)*8 + (e>>3))*4 + (k&3)]
// ---------------------------------------------------------------------------
__global__ void prep_kernel(const float* __restrict__ gate,
                            const float* __restrict__ w,
                            const float* __restrict__ b) {
    int e = blockIdx.x;
    int t = threadIdx.x;
    int ei = e & 7, txe = e >> 3;
    float sc = 0.f, sd = 0.f;
    for (int k = t; k < H; k += 256) {
        float gv = gate[e * H + k];
        float p  = gv * w[k];
        int kt = k >> 5, kb = (k >> 2) & 7, kq = k & 3;
        g_wp[(((kt * 8 + kb) * 64) + ei * 8 + txe) * 4 + kq] = p;
        sc += p;
        sd += b[k] * gv;
    }
    __shared__ float rs[256], rd[256];
    rs[t] = sc; rd[t] = sd;
    __syncthreads();
    for (int s = 128; s > 0; s >>= 1) {
        if (t < s) { rs[t] += rs[t + s]; rd[t] += rd[t + s]; }
        __syncthreads();
    }
    if (t == 0) { g_c[e] = rs[0]; g_d[e] = rd[0]; }
}

// packed f32x2 FMA (Blackwell): d = a*b + d elementwise on float pairs
__device__ __forceinline__ void ffma2(unsigned long long& d,
                                      unsigned long long a,
                                      unsigned long long b) {
    asm("fma.rn.f32x2 %0, %1, %2, %0;" : "+l"(d) : "l"(a), "l"(b));
}

// ---------------------------------------------------------------------------
// main: fused stats + GEMM (k-packed f32x2, kb-split halves) + softmax + top2
// grid = 128 blocks x 256 threads; per-thread tile = 8 rows x 8 experts
// half = t>>7: warps 0-3 do kb 0..3, warps 4-7 do kb 4..7 of every k-tile.
// tl = t&127; tx = tl&7 -> experts [8tx,8tx+8); r0 = (tl>>3)*8 -> 8 rows
// x smem (double buffer): slot = kb*128 + (row ^ kb)
// w smem (3-stage cp.async ring): slot = kb*64 + (e&7)*8 + (e>>3)
// ONE __syncthreads per k-tile. Final cross-half reduction through smem.
// ---------------------------------------------------------------------------
__global__ __launch_bounds__(NTHREADS, 1)
void router_kernel(const float* __restrict__ X, float* __restrict__ out,
                   int n_rows) {
    __shared__ float4 s_x[2][8 * 128];     // 32 KB (double buffer; reused as part[])
    __shared__ float4 s_w[3][8 * 64];      // 24 KB (cp.async 3-ring)
    __shared__ float s_mu[M_TILE], s_rstd[M_TILE];

    const int t = threadIdx.x;
    const int row_base = blockIdx.x * M_TILE;
    const int half = t >> 7;
    const int tl = t & 127;
    const int tx = tl & 7;
    const int r0 = (tl >> 3) * 8;
    const int kbb = half * 4;
    const int lrow = t >> 2;       // loader: 0..63 (rows lrow, lrow+64)
    const int lkq  = t & 3;        // loader: k segment (8 floats)

    uint32_t w_smem[3];
#pragma unroll
    for (int i = 0; i < 3; i++)
        w_smem[i] = (uint32_t)__cvta_generic_to_shared(&s_w[i][0]);

    const float* xg0 = X + (size_t)(row_base + lrow) * H + lkq * 8;

    unsigned long long acc[8][8];   // [ei][ri]
#pragma unroll
    for (int a = 0; a < 8; a++)
#pragma unroll
        for (int b2 = 0; b2 < 8; b2++) acc[a][b2] = 0ull;

    float st_s[2] = {0.f, 0.f};
    float st_q[2] = {0.f, 0.f};
    float4 xs[2][2];

    // prologue: w tile 0 via cp.async (ring 0), x tile 0 via LDG
    {
        const float* wsrc = g_wp + t * 4;
#pragma unroll
        for (int c = 0; c < 2; c++) {
            asm volatile("cp.async.cg.shared.global [%0], [%1], 16;\n"
                         :: "r"(w_smem[0] + (t + 256 * c) * 16), "l"(wsrc + 1024 * c));
        }
        asm volatile("cp.async.commit_group;\n" ::: "memory");
#pragma unroll
        for (int p = 0; p < 2; p++)
#pragma unroll
            for (int q = 0; q < 2; q++)
                xs[p][q] = *(const float4*)(xg0 + (size_t)p * 64 * H + q * 4);
    }

    for (int kt = 0; kt < NT; ++kt) {
        const int xb = kt & 1;
        // store x tile kt (swizzled) + accumulate LN stats from registers
#pragma unroll
        for (int p = 0; p < 2; p++) {
#pragma unroll
            for (int q = 0; q < 2; q++) {
                int kb = 2 * lkq + q;
                int row = lrow + 64 * p;
                s_x[xb][kb * 128 + (row ^ kb)] = xs[p][q];
                float4 v = xs[p][q];
                st_s[p] += (v.x + v.y) + (v.z + v.w);
                st_q[p] += v.x * v.x + v.y * v.y + v.z * v.z + v.w * v.w;
            }
        }
        // prefetch next tile: w -> next ring stage, x -> registers
        if (kt + 1 < NT) {
            const float* wsrc = g_wp + (size_t)(kt + 1) * 2048 + t * 4;
            int wi = (kt + 1) % 3;
#pragma unroll
            for (int c = 0; c < 2; c++) {
                asm volatile("cp.async.cg.shared.global [%0], [%1], 16;\n"
                             :: "r"(w_smem[wi] + (t + 256 * c) * 16), "l"(wsrc + 1024 * c));
            }
            asm volatile("cp.async.commit_group;\n" ::: "memory");
            const float* xgn = xg0 + (size_t)(kt + 1) * 32;
#pragma unroll
            for (int p = 0; p < 2; p++)
#pragma unroll
                for (int q = 0; q < 2; q++)
                    xs[p][q] = *(const float4*)(xgn + (size_t)p * 64 * H + q * 4);
            asm volatile("cp.async.wait_group 1;\n" ::: "memory");
        } else {
            asm volatile("cp.async.wait_group 0;\n" ::: "memory");
        }
        __syncthreads();

        // compute: this half does its 4 kb steps; 16 LDS.128 + 128 FFMA2 each
        const float4* wb = s_w[kt % 3];
#pragma unroll
        for (int j = 0; j < 4; j++) {
            const int kb = kbb + j;
            ulonglong2 xv[8], wv[8];
#pragma unroll
            for (int i = 0; i < 8; i++)
                xv[i] = *(const ulonglong2*)&s_x[xb][kb * 128 + r0 + (i ^ kb)];
#pragma unroll
            for (int i = 0; i < 8; i++)
                wv[i] = *(const ulonglong2*)&wb[kb * 64 + i * 8 + tx];
#pragma unroll
            for (int ei = 0; ei < 8; ei++)
#pragma unroll
                for (int ri = 0; ri < 8; ri++) {
                    ffma2(acc[ei][ri], xv[ri].x, wv[ei].x);
                    ffma2(acc[ei][ri], xv[ri].y, wv[ei].y);
                }
        }
    }

    // finalize LN stats (loader partners: lanes differing in bits 0-1)
#pragma unroll
    for (int p = 0; p < 2; p++) {
        float s = st_s[p], qq = st_q[p];
        s  += __shfl_xor_sync(0xffffffffu, s, 1);
        qq += __shfl_xor_sync(0xffffffffu, qq, 1);
        s  += __shfl_xor_sync(0xffffffffu, s, 2);
        qq += __shfl_xor_sync(0xffffffffu, qq, 2);
        if (lkq == 0) {
            float mu  = s * (1.0f / H);
            float var = qq * (1.0f / H) - mu * mu;
            s_mu[lrow + 64 * p]   = mu;
            s_rstd[lrow + 64 * p] = rsqrtf(var + 1e-5f);
        }
    }
    __syncthreads();   // all compute done; s_x free for reuse

    // cross-half reduction: upper half dumps pair-summed partials to smem
    float* part = (float*)&s_x[0][0];    // 128 rows x 64 experts floats = 32 KB
    if (half == 1) {
#pragma unroll
        for (int ri = 0; ri < 8; ri++) {
            int row = r0 + ri;
            float4 lo, hi;
            lo.x = __uint_as_float((unsigned)(acc[0][ri] & 0xffffffffull)) + __uint_as_float((unsigned)(acc[0][ri] >> 32));
            lo.y = __uint_as_float((unsigned)(acc[1][ri] & 0xffffffffull)) + __uint_as_float((unsigned)(acc[1][ri] >> 32));
            lo.z = __uint_as_float((unsigned)(acc[2][ri] & 0xffffffffull)) + __uint_as_float((unsigned)(acc[2][ri] >> 32));
            lo.w = __uint_as_float((unsigned)(acc[3][ri] & 0xffffffffull)) + __uint_as_float((unsigned)(acc[3][ri] >> 32));
            hi.x = __uint_as_float((unsigned)(acc[4][ri] & 0xffffffffull)) + __uint_as_float((unsigned)(acc[4][ri] >> 32));
            hi.y = __uint_as_float((unsigned)(acc[5][ri] & 0xffffffffull)) + __uint_as_float((unsigned)(acc[5][ri] >> 32));
            hi.z = __uint_as_float((unsigned)(acc[6][ri] & 0xffffffffull)) + __uint_as_float((unsigned)(acc[6][ri] >> 32));
            hi.w = __uint_as_float((unsigned)(acc[7][ri] & 0xffffffffull)) + __uint_as_float((unsigned)(acc[7][ri] >> 32));
            *(float4*)&part[row * 64 + 8 * tx]     = lo;
            *(float4*)&part[row * 64 + 8 * tx + 4] = hi;
        }
    }
    __syncthreads();
    if (half == 1) return;

    float cc[8], dd[8];
#pragma unroll
    for (int i = 0; i < 8; i++) { cc[i] = g_c[8 * tx + i]; dd[i] = g_d[8 * tx + i]; }

    float* out_p = out;                         // (N,2) normalized top-2 probs
    float* out_i = out + (size_t)n_rows * 2;    // (N,2) indices (as float)
    float* out_l = out + (size_t)n_rows * 4;    // (N,64) logits

#pragma unroll
    for (int ri = 0; ri < 8; ri++) {
        int row  = r0 + ri;
        int grow = row_base + row;
        float mu   = s_mu[row];
        float rstd = s_rstd[row];
        float4 plo = *(const float4*)&part[row * 64 + 8 * tx];
        float4 phi = *(const float4*)&part[row * 64 + 8 * tx + 4];
        float pother[8] = {plo.x, plo.y, plo.z, plo.w, phi.x, phi.y, phi.z, phi.w};
        float l[8];
#pragma unroll
        for (int ei = 0; ei < 8; ei++) {
            unsigned long long v = acc[ei][ri];
            float lv = __uint_as_float((unsigned)(v & 0xffffffffull)) +
                       __uint_as_float((unsigned)(v >> 32)) + pother[ei];
            lv = rstd * (lv - mu * cc[ei]) + dd[ei];
            l[ei] = fminf(fmaxf(lv, -10.0f), 10.0f);
        }
        *(float4*)&out_l[(size_t)grow * 64 + 8 * tx]     = make_float4(l[0], l[1], l[2], l[3]);
        *(float4*)&out_l[(size_t)grow * 64 + 8 * tx + 4] = make_float4(l[4], l[5], l[6], l[7]);

        // row max over 64 (8 local + width-8 butterfly over tx)
        float m = l[0];
#pragma unroll
        for (int i = 1; i < 8; i++) m = fmaxf(m, l[i]);
#pragma unroll
        for (int s8 = 4; s8; s8 >>= 1)
            m = fmaxf(m, __shfl_xor_sync(0xffffffffu, m, s8));

        float ev[8];
        float s = 0.f;
#pragma unroll
        for (int i = 0; i < 8; i++) { ev[i] = expf(l[i] - m); s += ev[i]; }
#pragma unroll
        for (int s8 = 4; s8; s8 >>= 1)
            s += __shfl_xor_sync(0xffffffffu, s, s8);

        // local top-2 (clip to [1e-4, 1] first, as reference does)
        float v1 = -1.f, v2 = -1.f; int i1 = 0, i2 = 0;
#pragma unroll
        for (int i = 0; i < 8; i++) {
            float p = ev[i] / s;
            p = fminf(fmaxf(p, 1e-4f), 1.0f);
            int gi = 8 * tx + i;
            if (p > v1) { v2 = v1; i2 = i1; v1 = p; i1 = gi; }
            else if (p > v2) { v2 = p; i2 = gi; }
        }
        // butterfly merge of top-2 lists, tie-break on lower index (jax top_k)
#pragma unroll
        for (int s8 = 4; s8; s8 >>= 1) {
            float u1 = __shfl_xor_sync(0xffffffffu, v1, s8);
            int   j1 = __shfl_xor_sync(0xffffffffu, i1, s8);
            float u2 = __shfl_xor_sync(0xffffffffu, v2, s8);
            int   j2 = __shfl_xor_sync(0xffffffffu, i2, s8);
            bool afirst = (v1 > u1) || (v1 == u1 && i1 < j1);
            float w1 = afirst ? v1 : u1;  int k1 = afirst ? i1 : j1;
            float ca = afirst ? v2 : u2;  int kca = afirst ? i2 : j2;  // winner's 2nd
            float cb = afirst ? u1 : v1;  int kcb = afirst ? j1 : i1;  // loser's 1st
            bool bsec = (cb > ca) || (cb == ca && kcb < kca);
            float w2 = bsec ? cb : ca;    int k2 = bsec ? kcb : kca;
            v1 = w1; i1 = k1; v2 = w2; i2 = k2;
        }
        if (tx == 0) {
            float ps = fmaxf(v1 + v2, 1e-4f);
            out_p[(size_t)grow * 2 + 0] = v1 / ps;
            out_p[(size_t)grow * 2 + 1] = v2 / ps;
            out_i[(size_t)grow * 2 + 0] = (float)i1;
            out_i[(size_t)grow * 2 + 1] = (float)i2;
        }
    }
}

extern "C" void kernel_launch(void* const* d_in, const int* in_sizes, int n_in,
                              void* d_out, int out_size) {
    const float* X = (const float*)d_in[0];   // hidden_states (4,4096,2048)
    const float* w = (const float*)d_in[1];   // ln_weight (2048)
    const float* b = (const float*)d_in[2];   // ln_bias (2048)
    const float* g = (const float*)d_in[3];   // gate_weight (64,2048)
    int n_rows = in_sizes[0] / H;             // 16384

    prep_kernel<<<E, 256>>>(g, w, b);
    router_kernel<<<n_rows / M_TILE, NTHREADS>>>(X, (float*)d_out, n_rows);
}

// round 13
// speedup vs baseline: 1.4802x; 1.1217x over previous
#include <cuda_runtime.h>
#include <cstdint>

#define H        2048
#define E        64
#define M_TILE   128
#define NT       64      // k tiles of 32
#define NTHREADS 256

// Prep outputs (static device scratch)
__device__ float g_wp[H * E];   // permuted: chunk(kt,kb, i=e&7, tx=e>>3)[kq]
__device__ float g_c[E];        // sum_h gate[e][h]*w[h]
__device__ float g_d[E];        // sum_h ln_bias[h]*gate[e][h]

// ---------------------------------------------------------------------------
// prep: fold ln_weight into gate, permute for conflict-free compute loads
// element (e, k) -> g_wp[(((k>>5)*8 + ((k>>2)&7))*64 + (e&7)*8 + (e>>3))*4 + (k&3)]
// ---------------------------------------------------------------------------
__global__ void prep_kernel(const float* __restrict__ gate,
                            const float* __restrict__ w,
                            const float* __restrict__ b) {
    int e = blockIdx.x;
    int t = threadIdx.x;
    int ei = e & 7, txe = e >> 3;
    float sc = 0.f, sd = 0.f;
    for (int k = t; k < H; k += 256) {
        float gv = gate[e * H + k];
        float p  = gv * w[k];
        int kt = k >> 5, kb = (k >> 2) & 7, kq = k & 3;
        g_wp[(((kt * 8 + kb) * 64) + ei * 8 + txe) * 4 + kq] = p;
        sc += p;
        sd += b[k] * gv;
    }
    __shared__ float rs[256], rd[256];
    rs[t] = sc; rd[t] = sd;
    __syncthreads();
    for (int s = 128; s > 0; s >>= 1) {
        if (t < s) { rs[t] += rs[t + s]; rd[t] += rd[t + s]; }
        __syncthreads();
    }
    if (t == 0) { g_c[e] = rs[0]; g_d[e] = rd[0]; }
}

// packed f32x2 FMA (Blackwell): d = a*b + d elementwise on float pairs
__device__ __forceinline__ void ffma2(unsigned long long& d,
                                      unsigned long long a,
                                      unsigned long long b) {
    asm("fma.rn.f32x2 %0, %1, %2, %0;" : "+l"(d) : "l"(a), "l"(b));
}

// ---------------------------------------------------------------------------
// main: fused stats + GEMM (k-packed f32x2) + softmax + top2
// grid = 128 blocks x 256 threads; thread tile = 4 rows x 8 experts
// tx = t&7 -> experts [8tx, 8tx+8);  r0 = (t>>3)*4 -> rows [r0, r0+4)
// x smem: slot = kb*128 + (row ^ kb)     (broadcast reads, conflict-free STS)
// w smem: slot = kb*64 + (e&7)*8 + (e>>3) (phase-consecutive reads)
// Inner loop software-pipelined: operands for step kb+1 load during kb's FMAs.
// ---------------------------------------------------------------------------
__global__ __launch_bounds__(NTHREADS, 1)
void router_kernel(const float* __restrict__ X, float* __restrict__ out,
                   int n_rows) {
    __shared__ float4 s_x[8 * 128];        // 16 KB
    __shared__ float4 s_w[2][8 * 64];      // 2 x 8 KB (cp.async double buffer)
    __shared__ float s_mu[M_TILE], s_rstd[M_TILE];

    const int t = threadIdx.x;
    const int row_base = blockIdx.x * M_TILE;
    const int tx = t & 7;
    const int r0 = (t >> 3) * 4;
    const int lrow = t >> 2;       // loader: 0..63 (rows lrow, lrow+64)
    const int lkq  = t & 3;        // loader: k segment (8 floats)

    uint32_t w_smem0 = (uint32_t)__cvta_generic_to_shared(&s_w[0][0]);
    uint32_t w_smem1 = (uint32_t)__cvta_generic_to_shared(&s_w[1][0]);

    const float* xg0 = X + (size_t)(row_base + lrow) * H + lkq * 8;

    unsigned long long acc[8][4];
#pragma unroll
    for (int a = 0; a < 8; a++)
#pragma unroll
        for (int b2 = 0; b2 < 4; b2++) acc[a][b2] = 0ull;

    float st_s[2] = {0.f, 0.f};
    float st_q[2] = {0.f, 0.f};
    float4 xs[2][2];

    // prologue: w tile 0 via cp.async, x tile 0 via LDG
    {
        const float* wsrc = g_wp + t * 4;
#pragma unroll
        for (int c = 0; c < 2; c++) {
            asm volatile("cp.async.cg.shared.global [%0], [%1], 16;\n"
                         :: "r"(w_smem0 + (t + 256 * c) * 16), "l"(wsrc + 1024 * c));
        }
        asm volatile("cp.async.commit_group;\n" ::: "memory");
#pragma unroll
        for (int p = 0; p < 2; p++)
#pragma unroll
            for (int q = 0; q < 2; q++)
                xs[p][q] = *(const float4*)(xg0 + (size_t)p * 64 * H + q * 4);
    }

    for (int kt = 0; kt < NT; ++kt) {
        __syncthreads();
        // store x tile kt (swizzled) + accumulate LN stats from registers
#pragma unroll
        for (int p = 0; p < 2; p++) {
#pragma unroll
            for (int q = 0; q < 2; q++) {
                int kb = 2 * lkq + q;
                int row = lrow + 64 * p;
                s_x[kb * 128 + (row ^ kb)] = xs[p][q];
                float4 v = xs[p][q];
                st_s[p] += (v.x + v.y) + (v.z + v.w);
                st_q[p] += v.x * v.x + v.y * v.y + v.z * v.z + v.w * v.w;
            }
        }
        // prefetch next tile: w -> other smem buffer, x -> registers
        if (kt + 1 < NT) {
            const float* wsrc = g_wp + (size_t)(kt + 1) * 2048 + t * 4;
            uint32_t wbase = ((kt + 1) & 1) ? w_smem1 : w_smem0;
#pragma unroll
            for (int c = 0; c < 2; c++) {
                asm volatile("cp.async.cg.shared.global [%0], [%1], 16;\n"
                             :: "r"(wbase + (t + 256 * c) * 16), "l"(wsrc + 1024 * c));
            }
            asm volatile("cp.async.commit_group;\n" ::: "memory");
            const float* xgn = xg0 + (size_t)(kt + 1) * 32;
#pragma unroll
            for (int p = 0; p < 2; p++)
#pragma unroll
                for (int q = 0; q < 2; q++)
                    xs[p][q] = *(const float4*)(xgn + (size_t)p * 64 * H + q * 4);
            asm volatile("cp.async.wait_group 1;\n" ::: "memory");
        } else {
            asm volatile("cp.async.wait_group 0;\n" ::: "memory");
        }
        __syncthreads();

        // compute: software-pipelined over kb; operands for kb+1 load during
        // kb's 64 FFMA2 (no dependency -> LDS latency hidden in-warp)
        const float4* wb = s_w[kt & 1];
        ulonglong2 xv[2][4], wv[2][8];
        // preload kb = 0
        {
            const int kb = 0;
            const int rbase = (r0 ^ (kb & 4));
#pragma unroll
            for (int i = 0; i < 4; i++)
                xv[0][i] = *(const ulonglong2*)&s_x[kb * 128 + rbase + (i ^ (kb & 3))];
#pragma unroll
            for (int i = 0; i < 8; i++)
                wv[0][i] = *(const ulonglong2*)&wb[kb * 64 + i * 8 + tx];
        }
#pragma unroll
        for (int kb = 0; kb < 8; kb++) {
            const int cur = kb & 1;
            const int nxt = cur ^ 1;
            if (kb < 7) {
                const int kn = kb + 1;
                const int rbase = (r0 ^ (kn & 4));
#pragma unroll
                for (int i = 0; i < 4; i++)
                    xv[nxt][i] = *(const ulonglong2*)&s_x[kn * 128 + rbase + (i ^ (kn & 3))];
#pragma unroll
                for (int i = 0; i < 8; i++)
                    wv[nxt][i] = *(const ulonglong2*)&wb[kn * 64 + i * 8 + tx];
            }
#pragma unroll
            for (int ei = 0; ei < 8; ei++)
#pragma unroll
                for (int ri = 0; ri < 4; ri++) {
                    ffma2(acc[ei][ri], xv[cur][ri].x, wv[cur][ei].x);
                    ffma2(acc[ei][ri], xv[cur][ri].y, wv[cur][ei].y);
                }
        }
    }

    // finalize LN stats (loader partners: lanes differing in bits 0-1)
#pragma unroll
    for (int p = 0; p < 2; p++) {
        float s = st_s[p], qq = st_q[p];
        s  += __shfl_xor_sync(0xffffffffu, s, 1);
        qq += __shfl_xor_sync(0xffffffffu, qq, 1);
        s  += __shfl_xor_sync(0xffffffffu, s, 2);
        qq += __shfl_xor_sync(0xffffffffu, qq, 2);
        if (lkq == 0) {
            float mu  = s * (1.0f / H);
            float var = qq * (1.0f / H) - mu * mu;
            s_mu[lrow + 64 * p]   = mu;
            s_rstd[lrow + 64 * p] = rsqrtf(var + 1e-5f);
        }
    }
    __syncthreads();

    float cc[8], dd[8];
#pragma unroll
    for (int i = 0; i < 8; i++) { cc[i] = g_c[8 * tx + i]; dd[i] = g_d[8 * tx + i]; }

    float* out_p = out;                         // (N,2) normalized top-2 probs
    float* out_i = out + (size_t)n_rows * 2;    // (N,2) indices (as float)
    float* out_l = out + (size_t)n_rows * 4;    // (N,64) logits

#pragma unroll
    for (int ri = 0; ri < 4; ri++) {
        int row  = r0 + ri;
        int grow = row_base + row;
        float mu   = s_mu[row];
        float rstd = s_rstd[row];
        float l[8];
#pragma unroll
        for (int ei = 0; ei < 8; ei++) {
            unsigned long long v = acc[ei][ri];
            float lv = __uint_as_float((unsigned int)(v & 0xffffffffull)) +
                       __uint_as_float((unsigned int)(v >> 32));
            lv = rstd * (lv - mu * cc[ei]) + dd[ei];
            l[ei] = fminf(fmaxf(lv, -10.0f), 10.0f);
        }
        *(float4*)&out_l[(size_t)grow * 64 + 8 * tx]     = make_float4(l[0], l[1], l[2], l[3]);
        *(float4*)&out_l[(size_t)grow * 64 + 8 * tx + 4] = make_float4(l[4], l[5], l[6], l[7]);

        // row max over 64 (8 local + width-8 butterfly over tx)
        float m = l[0];
#pragma unroll
        for (int i = 1; i < 8; i++) m = fmaxf(m, l[i]);
#pragma unroll
        for (int s8 = 4; s8; s8 >>= 1)
            m = fmaxf(m, __shfl_xor_sync(0xffffffffu, m, s8));

        float ev[8];
        float s = 0.f;
#pragma unroll
        for (int i = 0; i < 8; i++) { ev[i] = expf(l[i] - m); s += ev[i]; }
#pragma unroll
        for (int s8 = 4; s8; s8 >>= 1)
            s += __shfl_xor_sync(0xffffffffu, s, s8);

        // local top-2 (clip to [1e-4, 1] first, as reference does)
        float v1 = -1.f, v2 = -1.f; int i1 = 0, i2 = 0;
#pragma unroll
        for (int i = 0; i < 8; i++) {
            float p = ev[i] / s;
            p = fminf(fmaxf(p, 1e-4f), 1.0f);
            int gi = 8 * tx + i;
            if (p > v1) { v2 = v1; i2 = i1; v1 = p; i1 = gi; }
            else if (p > v2) { v2 = p; i2 = gi; }
        }
        // butterfly merge of top-2 lists, tie-break on lower index (jax top_k)
#pragma unroll
        for (int s8 = 4; s8; s8 >>= 1) {
            float u1 = __shfl_xor_sync(0xffffffffu, v1, s8);
            int   j1 = __shfl_xor_sync(0xffffffffu, i1, s8);
            float u2 = __shfl_xor_sync(0xffffffffu, v2, s8);
            int   j2 = __shfl_xor_sync(0xffffffffu, i2, s8);
            bool afirst = (v1 > u1) || (v1 == u1 && i1 < j1);
            float w1 = afirst ? v1 : u1;  int k1 = afirst ? i1 : j1;
            float ca = afirst ? v2 : u2;  int kca = afirst ? i2 : j2;  // winner's 2nd
            float cb = afirst ? u1 : v1;  int kcb = afirst ? j1 : i1;  // loser's 1st
            bool bsec = (cb > ca) || (cb == ca && kcb < kca);
            float w2 = bsec ? cb : ca;    int k2 = bsec ? kcb : kca;
            v1 = w1; i1 = k1; v2 = w2; i2 = k2;
        }
        if (tx == 0) {
            float ps = fmaxf(v1 + v2, 1e-4f);
            out_p[(size_t)grow * 2 + 0] = v1 / ps;
            out_p[(size_t)grow * 2 + 1] = v2 / ps;
            out_i[(size_t)grow * 2 + 0] = (float)i1;
            out_i[(size_t)grow * 2 + 1] = (float)i2;
        }
    }
}

extern "C" void kernel_launch(void* const* d_in, const int* in_sizes, int n_in,
                              void* d_out, int out_size) {
    const float* X = (const float*)d_in[0];   // hidden_states (4,4096,2048)
    const float* w = (const float*)d_in[1];   // ln_weight (2048)
    const float* b = (const float*)d_in[2];   // ln_bias (2048)
    const float* g = (const float*)d_in[3];   // gate_weight (64,2048)
    int n_rows = in_sizes[0] / H;             // 16384

    prep_kernel<<<E, 256>>>(g, w, b);
    router_kernel<<<n_rows / M_TILE, NTHREADS>>>(X, (float*)d_out, n_rows);
}